// round 3
// baseline (speedup 1.0000x reference)
#include <cuda_runtime.h>
#include <cuda_bf16.h>

// ConvQuadInterp3d: 27-point stencil keypoint refinement, 4 outputs/thread in w.
// x: (B=2, CH=1, D=10, H=512, W=512) fp32
// out: coords (B,1,3,D,H,W) then y_max (B,1,D,H,W), concatenated fp32.

#define Bb 2
#define Dd 10
#define Hh 512
#define Ww 512
#define TW 128           // tile width  (32 threads x 4 outputs)
#define TH 8             // tile height
#define BX 32
#define BY 8
#define NTHREADS 256
#define SP 132           // smem row stride in floats (16B-aligned rows)
#define SR (TH + 2)      // 10 halo rows
#define SLICE (SR * SP)  // 1320 floats per slice

__device__ __forceinline__ int clampi(int v, int lo, int hi) {
    return min(max(v, lo), hi);
}

// load 6 consecutive floats starting at 16B-aligned si
#define LD6(rowptr, v) do {                                          \
    float4 _q = *(const float4*)((rowptr) + si);                     \
    float2 _e = *(const float2*)((rowptr) + si + 4);                 \
    (v)[0]=_q.x; (v)[1]=_q.y; (v)[2]=_q.z; (v)[3]=_q.w;              \
    (v)[4]=_e.x; (v)[5]=_e.y;                                        \
} while(0)

__global__ __launch_bounds__(NTHREADS, 3)
void cqi_kernel(const float* __restrict__ x, float* __restrict__ out)
{
    __shared__ __align__(16) float buf[3][SR][SP];

    const int w0 = blockIdx.x * TW;
    const int h0 = blockIdx.y * TH;
    const int b  = blockIdx.z;
    const int tx = threadIdx.x, ty = threadIdx.y;
    const int tid = ty * BX + tx;

    const size_t plane = (size_t)Hh * Ww;
    const float* xb = x + (size_t)b * Dd * plane;

    float* coords = out;
    float* ymax   = out + (size_t)Bb * 3 * Dd * plane;

    // Per-thread slice-load slots (constant across d). Slots 0..4 always valid.
    int gOff[6];
    #pragma unroll
    for (int i = 0; i < 6; ++i) {
        int idx = tid + i * NTHREADS;
        int row = idx / SP, col = idx % SP;
        gOff[i] = clampi(h0 - 1 + row, 0, Hh - 1) * Ww + clampi(w0 - 1 + col, 0, Ww - 1);
    }
    const bool v5 = (tid < SLICE - 5 * NTHREADS);  // tid < 40

    // Prologue: slices -1, 0, 1 into buf[0..2]
    #pragma unroll
    for (int s = 0; s < 3; ++s) {
        const float* src = xb + (size_t)clampi(s - 1, 0, Dd - 1) * plane;
        float* dst = &buf[s][0][0];
        #pragma unroll
        for (int i = 0; i < 5; ++i) dst[tid + i * NTHREADS] = __ldg(src + gOff[i]);
        if (v5) dst[tid + 5 * NTHREADS] = __ldg(src + gOff[5]);
    }

    int pz = 0, cz = 1, nz = 2;

    const int h  = h0 + ty;
    const int wb = w0 + 4 * tx;
    const int si = 4 * tx;  // leftmost needed smem col (s=0 <-> w0-1)

    #pragma unroll 1
    for (int d = 0; d < Dd; ++d) {
        // Prefetch slice d+2 into registers
        const float* src = xb + (size_t)clampi(d + 2, 0, Dd - 1) * plane;
        float r[6];
        #pragma unroll
        for (int i = 0; i < 5; ++i) r[i] = __ldg(src + gOff[i]);
        r[5] = v5 ? __ldg(src + gOff[5]) : 0.0f;

        __syncthreads();

        const float* Pr0 = &buf[pz][ty    ][0];
        const float* Pr1 = &buf[pz][ty + 1][0];
        const float* Pr2 = &buf[pz][ty + 2][0];
        const float* Cr0 = &buf[cz][ty    ][0];
        const float* Cr1 = &buf[cz][ty + 1][0];
        const float* Cr2 = &buf[cz][ty + 2][0];
        const float* Nr0 = &buf[nz][ty    ][0];
        const float* Nr1 = &buf[nz][ty + 1][0];
        const float* Nr2 = &buf[nz][ty + 2][0];

        // Build per-row slice-folded maxes + raw center row of C + P/N center-col max
        float s0[6], s1[6], s2[6], c1[6], pn[4], t[6];
        LD6(Pr0, s0);
        LD6(Pr1, s1);
        #pragma unroll
        for (int j = 0; j < 4; ++j) pn[j] = s1[j + 1];
        LD6(Pr2, s2);
        LD6(Cr0, t);
        #pragma unroll
        for (int j = 0; j < 6; ++j) s0[j] = fmaxf(s0[j], t[j]);
        LD6(Cr1, c1);
        #pragma unroll
        for (int j = 0; j < 6; ++j) s1[j] = fmaxf(s1[j], c1[j]);
        LD6(Cr2, t);
        #pragma unroll
        for (int j = 0; j < 6; ++j) s2[j] = fmaxf(s2[j], t[j]);
        LD6(Nr0, t);
        #pragma unroll
        for (int j = 0; j < 6; ++j) s0[j] = fmaxf(s0[j], t[j]);
        LD6(Nr1, t);
        #pragma unroll
        for (int j = 0; j < 6; ++j) s1[j] = fmaxf(s1[j], t[j]);
        #pragma unroll
        for (int j = 0; j < 4; ++j) pn[j] = fmaxf(pn[j], t[j + 1]);
        LD6(Nr2, t);
        #pragma unroll
        for (int j = 0; j < 6; ++j) s2[j] = fmaxf(s2[j], t[j]);

        // Pairwise window maxes for rows 0 and 2 (all slices folded)
        float pr0[5], pr2[5];
        #pragma unroll
        for (int j = 0; j < 5; ++j) {
            pr0[j] = fmaxf(s0[j], s0[j + 1]);
            pr2[j] = fmaxf(s2[j], s2[j + 1]);
        }

        float od[4], oh[4], ow[4], oy[4];

        #pragma unroll
        for (int k = 0; k < 4; ++k) {
            const float cc = c1[k + 1];
            float nm = fmaxf(fmaxf(pr0[k], pr0[k + 1]),
                             fmaxf(pr2[k], pr2[k + 1]));
            nm = fmaxf(nm, fmaxf(s1[k], s1[k + 2]));
            nm = fmaxf(nm, pn[k]);
            nm = fmaxf(nm, 0.0f);
            const bool m = (cc > nm);

            float dx0 = 0.0f, dx1 = 0.0f, dx2 = 0.0f, yv = cc;

            if (__ballot_sync(0xFFFFFFFFu, m)) {
                const int ci = si + k;
                // reload needed scalars from smem (rare path)
                const float ca0 = Cr0[ci], ca1 = Cr0[ci + 1], ca2 = Cr0[ci + 2];
                const float cb0 = Cr2[ci], cb1 = Cr2[ci + 1], cb2 = Cr2[ci + 2];
                const float p0  = Pr1[ci], p1v = Pr1[ci + 1], p2  = Pr1[ci + 2];
                const float n0  = Nr1[ci], n1v = Nr1[ci + 1], n2  = Nr1[ci + 2];
                const float pa  = Pr0[ci + 1], pb = Pr2[ci + 1];
                const float na  = Nr0[ci + 1], nb = Nr2[ci + 1];

                const float gx = 0.5f * (c1[k + 2] - c1[k]);
                const float gy = 0.5f * (cb1 - ca1);
                const float gs = 0.5f * (n1v - p1v);
                const float dxx = c1[k] + c1[k + 2] - 2.0f * cc;
                const float dyy = ca1 + cb1 - 2.0f * cc;
                const float dss = p1v + n1v - 2.0f * cc;
                const float dxy = 0.25f * (ca0 + cb2 - cb0 - ca2);
                const float dys = 0.25f * (pa + nb - na - pb);
                const float dxs = 0.25f * (p0 + n2 - n0 - p2);

                const float h00 = m ? dxx : 1.0f;
                const float h01 = m ? dxy : 0.0f;
                const float h02 = m ? dxs : 0.0f;
                const float h11 = m ? dyy : 1.0f;
                const float h12 = m ? dys : 0.0f;
                const float h22 = m ? dss : 1.0f;
                const float h10 = h01, h20 = h02, h21 = h12;
                const float b0 = m ? gx : 0.0f;
                const float b1 = m ? gy : 0.0f;
                const float b2 = m ? gs : 0.0f;

                const float c00 = h11 * h22 - h12 * h21;
                const float c01 = h10 * h22 - h12 * h20;
                const float c02 = h10 * h21 - h11 * h20;
                const float det = h00 * c00 - h01 * c01 + h02 * c02;
                const float inv = 1.0f / det;

                const float t0 = b1 * h22 - h12 * b2;
                const float t1 = b1 * h21 - h11 * b2;
                const float t2 = h10 * b2 - b1 * h20;

                const float sx = (b0 * c00 - h01 * t0 + h02 * t1) * inv;
                const float sy = (h00 * t0 - b0 * c01 + h02 * t2) * inv;
                const float ss = (h00 * (h11 * b2 - h21 * b1)
                                - h01 * (h10 * b2 - h20 * b1)
                                + b0 * c02) * inv;

                dx0 = -sx; dx1 = -sy; dx2 = -ss;
                const float mag = fmaxf(fmaxf(fabsf(dx0), fabsf(dx1)), fabsf(dx2));
                if (mag > 0.7f) { dx0 = 0.0f; dx1 = 0.0f; dx2 = 0.0f; }

                const float dy_ = 0.5f * (gx * dx0 + gy * dx1 + gs * dx2);
                yv = cc + dy_ + (m ? 10.0f : 0.0f);
            }

            od[k] = (float)d + dx2;
            oh[k] = (float)h + dx1;
            ow[k] = (float)(wb + k) + dx0;
            oy[k] = yv;
        }

        // Vectorized stores
        const size_t basep = (size_t)d * plane + (size_t)h * Ww + wb;
        float* c0p = coords + (size_t)(b * 3 + 0) * Dd * plane + basep;
        float* c1p = coords + (size_t)(b * 3 + 1) * Dd * plane + basep;
        float* c2p = coords + (size_t)(b * 3 + 2) * Dd * plane + basep;
        float* yp  = ymax   + (size_t)b * Dd * plane + basep;
        *(float4*)c0p = make_float4(od[0], od[1], od[2], od[3]);
        *(float4*)c1p = make_float4(oh[0], oh[1], oh[2], oh[3]);
        *(float4*)c2p = make_float4(ow[0], ow[1], ow[2], ow[3]);
        *(float4*)yp  = make_float4(oy[0], oy[1], oy[2], oy[3]);

        __syncthreads();

        // Rotate and deposit prefetched slice d+2
        const int t0z = pz; pz = cz; cz = nz; nz = t0z;
        float* nf = &buf[nz][0][0];
        #pragma unroll
        for (int i = 0; i < 5; ++i) nf[tid + i * NTHREADS] = r[i];
        if (v5) nf[tid + 5 * NTHREADS] = r[5];
    }
}

extern "C" void kernel_launch(void* const* d_in, const int* in_sizes, int n_in,
                              void* d_out, int out_size)
{
    const float* x = (const float*)d_in[0];
    float* out = (float*)d_out;
    dim3 grid(Ww / TW, Hh / TH, Bb);   // (4, 64, 2)
    dim3 block(BX, BY);                // (32, 8)
    cqi_kernel<<<grid, block>>>(x, out);
}

// round 6
// speedup vs baseline: 1.0062x; 1.0062x over previous
#include <cuda_runtime.h>
#include <cuda_bf16.h>

// ConvQuadInterp3d, two-phase: dense max-detect + defaults, then sparse solve.
// x: (B=2, CH=1, D=10, H=512, W=512) fp32
// out: coords (B,1,3,D,H,W) then y_max (B,1,D,H,W), concatenated fp32.

#define Bb 2
#define Dd 10
#define Hh 512
#define Ww 512
#define TW 128           // tile width  (32 threads x 4 outputs)
#define TH 8             // tile height
#define BX 32
#define BY 8
#define NTHREADS 256
#define SP 132           // smem row stride (floats), keeps 16B row alignment
#define SR (TH + 2)      // 10 halo rows
#define SLICE (SR * SP)  // 1320 floats per slice
#define LCAP 1312        // per-CTA max maxima: ceil(10/2)*ceil(8/2)*ceil(128/2)=1280

#define GCAP (655360 + 2048)
__device__ unsigned g_count;
__device__ unsigned g_idx[GCAP];

__device__ __forceinline__ int clampi(int v, int lo, int hi) {
    return min(max(v, lo), hi);
}

__global__ void init_kernel() { g_count = 0u; }

// load 6 consecutive floats starting at 16B-aligned si
#define LD6(rowptr, v) do {                                          \
    float4 _q = *(const float4*)((rowptr) + si);                     \
    float2 _e = *(const float2*)((rowptr) + si + 4);                 \
    (v)[0]=_q.x; (v)[1]=_q.y; (v)[2]=_q.z; (v)[3]=_q.w;              \
    (v)[4]=_e.x; (v)[5]=_e.y;                                        \
} while(0)

__global__ __launch_bounds__(NTHREADS, 5)
void phase1_kernel(const float* __restrict__ x, float* __restrict__ out)
{
    __shared__ __align__(16) float buf[3][SR][SP];
    __shared__ unsigned s_list[LCAP];
    __shared__ unsigned s_cnt, s_base;

    const int w0 = blockIdx.x * TW;
    const int h0 = blockIdx.y * TH;
    const int b  = blockIdx.z;
    const int tx = threadIdx.x, ty = threadIdx.y;
    const int tid = ty * BX + tx;

    if (tid == 0) s_cnt = 0u;

    const size_t plane = (size_t)Hh * Ww;
    const float* xb = x + (size_t)b * Dd * plane;

    float* coords = out;
    float* ymax   = out + (size_t)Bb * 3 * Dd * plane;

    // Per-thread slice-load slots (constant across d). Slots 0..4 always valid.
    int gOff[6];
    #pragma unroll
    for (int i = 0; i < 6; ++i) {
        int idx = tid + i * NTHREADS;
        int row = idx / SP, col = idx % SP;
        gOff[i] = clampi(h0 - 1 + row, 0, Hh - 1) * Ww + clampi(w0 - 1 + col, 0, Ww - 1);
    }
    const bool v5 = (tid < SLICE - 5 * NTHREADS);  // tid < 40

    // Prologue: slices -1, 0, 1 into buf[0..2] (clamped in d)
    #pragma unroll
    for (int s = 0; s < 3; ++s) {
        const float* src = xb + (size_t)clampi(s - 1, 0, Dd - 1) * plane;
        float* dst = &buf[s][0][0];
        #pragma unroll
        for (int i = 0; i < 5; ++i) dst[tid + i * NTHREADS] = __ldg(src + gOff[i]);
        if (v5) dst[tid + 5 * NTHREADS] = __ldg(src + gOff[5]);
    }

    int pz = 0, cz = 1, nz = 2;

    const int h  = h0 + ty;
    const int wb = w0 + 4 * tx;
    const int si = 4 * tx;  // smem col of (w-1) for first output

    #pragma unroll 1
    for (int d = 0; d < Dd; ++d) {
        __syncthreads();  // slices d-1,d,d+1 ready

        const float* Pr = &buf[pz][ty][0];
        const float* Cr = &buf[cz][ty][0];
        const float* Nr = &buf[nz][ty][0];

        // A[j] = max over {P,C,N} of rows 0 and 2 (6 row-loads folded)
        // pn[j] = max(P_row1[j], N_row1[j]); c1[j] = C_row1[j] (raw)
        float A[6], pn[6], c1[6], t[6];
        LD6(Pr, A);
        LD6(Pr + 2 * SP, t);
        #pragma unroll
        for (int j = 0; j < 6; ++j) A[j] = fmaxf(A[j], t[j]);
        LD6(Cr, t);
        #pragma unroll
        for (int j = 0; j < 6; ++j) A[j] = fmaxf(A[j], t[j]);
        LD6(Cr + 2 * SP, t);
        #pragma unroll
        for (int j = 0; j < 6; ++j) A[j] = fmaxf(A[j], t[j]);
        LD6(Nr, t);
        #pragma unroll
        for (int j = 0; j < 6; ++j) A[j] = fmaxf(A[j], t[j]);
        LD6(Nr + 2 * SP, t);
        #pragma unroll
        for (int j = 0; j < 6; ++j) A[j] = fmaxf(A[j], t[j]);
        LD6(Pr + SP, pn);
        LD6(Nr + SP, t);
        #pragma unroll
        for (int j = 0; j < 6; ++j) pn[j] = fmaxf(pn[j], t[j]);
        LD6(Cr + SP, c1);

        // Per-output strict-max test + default outputs
        #pragma unroll
        for (int k = 0; k < 4; ++k) {
            float nm = fmaxf(fmaxf(A[k], A[k + 1]), A[k + 2]);
            nm = fmaxf(nm, fmaxf(c1[k], c1[k + 2]));
            nm = fmaxf(nm, fmaxf(fmaxf(pn[k], pn[k + 1]), pn[k + 2]));
            nm = fmaxf(nm, 0.0f);
            if (c1[k + 1] > nm) {
                unsigned slot = atomicAdd(&s_cnt, 1u);
                if (slot < LCAP)
                    s_list[slot] = ((((unsigned)(b) << 4 | (unsigned)d) << 9
                                     | (unsigned)h) << 9) | (unsigned)(wb + k);
            }
        }

        const size_t basep = (size_t)d * plane + (size_t)h * Ww + wb;
        const float fd = (float)d, fh = (float)h, fw = (float)wb;
        *(float4*)(coords + (size_t)(b * 3 + 0) * Dd * plane + basep)
            = make_float4(fd, fd, fd, fd);
        *(float4*)(coords + (size_t)(b * 3 + 1) * Dd * plane + basep)
            = make_float4(fh, fh, fh, fh);
        *(float4*)(coords + (size_t)(b * 3 + 2) * Dd * plane + basep)
            = make_float4(fw, fw + 1.0f, fw + 2.0f, fw + 3.0f);
        *(float4*)(ymax + (size_t)b * Dd * plane + basep)
            = make_float4(c1[1], c1[2], c1[3], c1[4]);

        __syncthreads();  // reads done before overwriting oldest slice

        // Rotate; load slice d+2 (clamped) directly into the freed buffer
        const int t0z = pz; pz = cz; cz = nz; nz = t0z;
        const float* src = xb + (size_t)clampi(d + 2, 0, Dd - 1) * plane;
        float* nf = &buf[nz][0][0];
        #pragma unroll
        for (int i = 0; i < 5; ++i) nf[tid + i * NTHREADS] = __ldg(src + gOff[i]);
        if (v5) nf[tid + 5 * NTHREADS] = __ldg(src + gOff[5]);
    }

    // Flush per-CTA maxima list to global
    __syncthreads();
    if (tid == 0) s_base = atomicAdd(&g_count, s_cnt);
    __syncthreads();
    const unsigned cnt = s_cnt, base = s_base;
    for (unsigned i = tid; i < cnt; i += NTHREADS)
        g_idx[base + i] = s_list[i];
}

__global__ __launch_bounds__(128)
void phase2_kernel(const float* __restrict__ x, float* __restrict__ out)
{
    const unsigned cnt = g_count;
    const size_t plane = (size_t)Hh * Ww;
    float* coords = out;
    float* ymax   = out + (size_t)Bb * 3 * Dd * plane;

    for (unsigned i = blockIdx.x * blockDim.x + threadIdx.x; i < cnt;
         i += gridDim.x * blockDim.x)
    {
        const unsigned e = g_idx[i];
        const int w = e & 511;
        const int h = (e >> 9) & 511;
        const int d = (e >> 18) & 15;
        const int b = (int)(e >> 22);

        const float* xb = x + (size_t)b * Dd * plane;
        size_t zo[3]; int yo[3], xo[3];
        #pragma unroll
        for (int j = 0; j < 3; ++j) {
            zo[j] = (size_t)clampi(d - 1 + j, 0, Dd - 1) * plane;
            yo[j] = clampi(h - 1 + j, 0, Hh - 1) * Ww;
            xo[j] = clampi(w - 1 + j, 0, Ww - 1);
        }
        #define V(z,y,xx) __ldg(xb + zo[z] + yo[y] + xo[xx])

        const float cc   = V(1,1,1);
        const float v110 = V(1,1,0), v112 = V(1,1,2);
        const float v101 = V(1,0,1), v121 = V(1,2,1);
        const float v011 = V(0,1,1), v211 = V(2,1,1);
        const float v100 = V(1,0,0), v122 = V(1,2,2), v120 = V(1,2,0), v102 = V(1,0,2);
        const float v001 = V(0,0,1), v221 = V(2,2,1), v201 = V(2,0,1), v021 = V(0,2,1);
        const float v010 = V(0,1,0), v212 = V(2,1,2), v210 = V(2,1,0), v012 = V(0,1,2);
        #undef V

        const float gx = 0.5f * (v112 - v110);
        const float gy = 0.5f * (v121 - v101);
        const float gs = 0.5f * (v211 - v011);
        const float h00 = v110 + v112 - 2.0f * cc;
        const float h11 = v101 + v121 - 2.0f * cc;
        const float h22 = v011 + v211 - 2.0f * cc;
        const float h01 = 0.25f * (v100 + v122 - v120 - v102);
        const float h12 = 0.25f * (v001 + v221 - v201 - v021);
        const float h02 = 0.25f * (v010 + v212 - v210 - v012);
        const float h10 = h01, h20 = h02, h21 = h12;
        const float b0 = gx, b1 = gy, b2 = gs;

        const float c00 = h11 * h22 - h12 * h21;
        const float c01 = h10 * h22 - h12 * h20;
        const float c02 = h10 * h21 - h11 * h20;
        const float det = h00 * c00 - h01 * c01 + h02 * c02;
        const float inv = 1.0f / det;

        const float t0 = b1 * h22 - h12 * b2;
        const float t1 = b1 * h21 - h11 * b2;
        const float t2 = h10 * b2 - b1 * h20;

        const float sx = (b0 * c00 - h01 * t0 + h02 * t1) * inv;
        const float sy = (h00 * t0 - b0 * c01 + h02 * t2) * inv;
        const float ss = (h00 * (h11 * b2 - h21 * b1)
                        - h01 * (h10 * b2 - h20 * b1)
                        + b0 * c02) * inv;

        float dx0 = -sx, dx1 = -sy, dx2 = -ss;
        const float mag = fmaxf(fmaxf(fabsf(dx0), fabsf(dx1)), fabsf(dx2));
        if (mag > 0.7f) { dx0 = 0.0f; dx1 = 0.0f; dx2 = 0.0f; }

        const float dy_ = 0.5f * (gx * dx0 + gy * dx1 + gs * dx2);
        const float yv  = cc + dy_ + 10.0f;

        const size_t basep = (size_t)d * plane + (size_t)h * Ww + w;
        coords[(size_t)(b * 3 + 0) * Dd * plane + basep] = (float)d + dx2;
        coords[(size_t)(b * 3 + 1) * Dd * plane + basep] = (float)h + dx1;
        coords[(size_t)(b * 3 + 2) * Dd * plane + basep] = (float)w + dx0;
        ymax[(size_t)b * Dd * plane + basep] = yv;
    }
}

extern "C" void kernel_launch(void* const* d_in, const int* in_sizes, int n_in,
                              void* d_out, int out_size)
{
    const float* x = (const float*)d_in[0];
    float* out = (float*)d_out;

    init_kernel<<<1, 1>>>();

    dim3 grid1(Ww / TW, Hh / TH, Bb);   // (4, 64, 2)
    dim3 block1(BX, BY);                // (32, 8)
    phase1_kernel<<<grid1, block1>>>(x, out);

    phase2_kernel<<<1024, 128>>>(x, out);
}

// round 7
// speedup vs baseline: 1.4178x; 1.4091x over previous
#include <cuda_runtime.h>
#include <cuda_bf16.h>

// ConvQuadInterp3d single-kernel: register-resident separable 27-max + rare inline solve.
// x: (B=2, CH=1, D=10, H=512, W=512) fp32
// out: coords (B,1,3,D,H,W) then y_max (B,1,D,H,W), concatenated fp32.

#define Bb 2
#define Dd 10
#define Hh 512
#define Ww 512
#define PLANE (Hh * Ww)     // 262144
#define WCOLS 18            // ceil(512 / 30)
#define STRIP 8
#define NW 8                // warps per block

__device__ __forceinline__ int clampi(int v, int lo, int hi) {
    return min(max(v, lo), hi);
}

__global__ __launch_bounds__(256)
void cqi_kernel(const float* __restrict__ x, float* __restrict__ out)
{
    const int lane  = threadIdx.x;                 // 0..31
    const int wid   = threadIdx.y;                 // 0..7
    const int c     = blockIdx.x;                  // 0..17 warp-columns
    const int strip = blockIdx.y * NW + wid;       // 0..63
    const int b     = blockIdx.z;
    const int h0    = strip * STRIP;
    const int w     = c * 30 + lane - 1;           // lanes 0,31 are halo
    const int wc    = clampi(w, 0, Ww - 1);
    const bool valid = (lane >= 1) && (lane <= 30) && (w < Ww);

    const float* xb = x + b * Dd * PLANE;
    float* ymax = out + Bb * 3 * Dd * PLANE;

    float x0[Dd], zm1[Dd], z0[Dd];

    // Prologue: rows h0-1 (zmax only) and h0 (raw + zmax)
    {
        const float* p = xb + clampi(h0 - 1, 0, Hh - 1) * Ww + wc;
        float t[Dd];
        #pragma unroll
        for (int d = 0; d < Dd; ++d) t[d] = __ldg(p + d * PLANE);
        #pragma unroll
        for (int d = 0; d < Dd; ++d)
            zm1[d] = fmaxf(fmaxf(t[d > 0 ? d - 1 : 0], t[d]), t[d < Dd - 1 ? d + 1 : Dd - 1]);
        p = xb + h0 * Ww + wc;
        #pragma unroll
        for (int d = 0; d < Dd; ++d) x0[d] = __ldg(p + d * PLANE);
        #pragma unroll
        for (int d = 0; d < Dd; ++d)
            z0[d] = fmaxf(fmaxf(x0[d > 0 ? d - 1 : 0], x0[d]), x0[d < Dd - 1 ? d + 1 : Dd - 1]);
    }

    #pragma unroll 1
    for (int hh = 0; hh < STRIP; ++hh) {
        const int h = h0 + hh;

        // Load row h+1 (clamped), fold z
        const float* p = xb + clampi(h + 1, 0, Hh - 1) * Ww + wc;
        float xn[Dd], zp1[Dd];
        #pragma unroll
        for (int d = 0; d < Dd; ++d) xn[d] = __ldg(p + d * PLANE);
        #pragma unroll
        for (int d = 0; d < Dd; ++d)
            zp1[d] = fmaxf(fmaxf(xn[d > 0 ? d - 1 : 0], xn[d]), xn[d < Dd - 1 ? d + 1 : Dd - 1]);

        const int hb = h * Ww + w;
        float* c0p = out + (b * 3 + 0) * Dd * PLANE + hb;
        float* c1p = out + (b * 3 + 1) * Dd * PLANE + hb;
        float* c2p = out + (b * 3 + 2) * Dd * PLANE + hb;
        float* yp  = ymax + b * Dd * PLANE + hb;

        unsigned mask = 0u;

        #pragma unroll
        for (int d = 0; d < Dd; ++d) {
            // full 3x3 (z,y) column max at own w (shared with neighbors via shfl)
            const float cmf = fmaxf(fmaxf(zm1[d], z0[d]), zp1[d]);
            const float Lv = __shfl_up_sync(0xFFFFFFFFu, cmf, 1);
            const float Rv = __shfl_down_sync(0xFFFFFFFFu, cmf, 1);
            // own-column 8-neighbor max (excludes center)
            const float zpn = fmaxf(x0[d > 0 ? d - 1 : 0], x0[d < Dd - 1 ? d + 1 : Dd - 1]);
            float nm = fmaxf(fmaxf(zm1[d], zp1[d]), zpn);
            nm = fmaxf(nm, fmaxf(Lv, Rv));
            nm = fmaxf(nm, 0.0f);
            const float cc = x0[d];
            if (valid) {
                if (cc > nm) mask |= 1u << d;
                c0p[d * PLANE] = (float)d;
                c1p[d * PLANE] = (float)h;
                c2p[d * PLANE] = (float)w;
                yp [d * PLANE] = cc;
            }
        }

        // Rare path: quadratic refinement at strict maxima (single code copy)
        while (mask) {
            const int d = __ffs(mask) - 1;
            mask &= mask - 1u;

            int zo[3], yo[3], xo[3];
            #pragma unroll
            for (int j = 0; j < 3; ++j) {
                zo[j] = clampi(d - 1 + j, 0, Dd - 1) * PLANE;
                yo[j] = clampi(h - 1 + j, 0, Hh - 1) * Ww;
                xo[j] = clampi(w - 1 + j, 0, Ww - 1);
            }
            #define V(z, y, xx) __ldg(xb + zo[z] + yo[y] + xo[xx])
            const float cc   = V(1,1,1);
            const float v110 = V(1,1,0), v112 = V(1,1,2);
            const float v101 = V(1,0,1), v121 = V(1,2,1);
            const float v011 = V(0,1,1), v211 = V(2,1,1);
            const float v100 = V(1,0,0), v122 = V(1,2,2), v120 = V(1,2,0), v102 = V(1,0,2);
            const float v001 = V(0,0,1), v221 = V(2,2,1), v201 = V(2,0,1), v021 = V(0,2,1);
            const float v010 = V(0,1,0), v212 = V(2,1,2), v210 = V(2,1,0), v012 = V(0,1,2);
            #undef V

            const float gx = 0.5f * (v112 - v110);
            const float gy = 0.5f * (v121 - v101);
            const float gs = 0.5f * (v211 - v011);
            const float h00 = v110 + v112 - 2.0f * cc;
            const float h11 = v101 + v121 - 2.0f * cc;
            const float h22 = v011 + v211 - 2.0f * cc;
            const float h01 = 0.25f * (v100 + v122 - v120 - v102);
            const float h12 = 0.25f * (v001 + v221 - v201 - v021);
            const float h02 = 0.25f * (v010 + v212 - v210 - v012);
            const float h10 = h01, h20 = h02, h21 = h12;
            const float b0 = gx, b1 = gy, b2 = gs;

            const float c00 = h11 * h22 - h12 * h21;
            const float c01 = h10 * h22 - h12 * h20;
            const float c02 = h10 * h21 - h11 * h20;
            const float det = h00 * c00 - h01 * c01 + h02 * c02;
            const float inv = 1.0f / det;

            const float t0 = b1 * h22 - h12 * b2;
            const float t1 = b1 * h21 - h11 * b2;
            const float t2 = h10 * b2 - b1 * h20;

            const float sx = (b0 * c00 - h01 * t0 + h02 * t1) * inv;
            const float sy = (h00 * t0 - b0 * c01 + h02 * t2) * inv;
            const float ss = (h00 * (h11 * b2 - h21 * b1)
                            - h01 * (h10 * b2 - h20 * b1)
                            + b0 * c02) * inv;

            float dx0 = -sx, dx1 = -sy, dx2 = -ss;
            const float mag = fmaxf(fmaxf(fabsf(dx0), fabsf(dx1)), fabsf(dx2));
            if (mag > 0.7f) { dx0 = 0.0f; dx1 = 0.0f; dx2 = 0.0f; }

            const float dy_ = 0.5f * (gx * dx0 + gy * dx1 + gs * dx2);
            const float yv  = cc + dy_ + 10.0f;

            c0p[d * PLANE] = (float)d + dx2;
            c1p[d * PLANE] = (float)h + dx1;
            c2p[d * PLANE] = (float)w + dx0;
            yp [d * PLANE] = yv;
        }

        // Rotate rolling state
        #pragma unroll
        for (int d = 0; d < Dd; ++d) {
            zm1[d] = z0[d];
            z0[d]  = zp1[d];
            x0[d]  = xn[d];
        }
    }
}

extern "C" void kernel_launch(void* const* d_in, const int* in_sizes, int n_in,
                              void* d_out, int out_size)
{
    const float* x = (const float*)d_in[0];
    float* out = (float*)d_out;
    dim3 grid(WCOLS, Hh / STRIP / NW, Bb);   // (18, 8, 2)
    dim3 block(32, NW);                      // 256 threads
    cqi_kernel<<<grid, block>>>(x, out);
}

// round 8
// speedup vs baseline: 1.4272x; 1.0066x over previous
#include <cuda_runtime.h>
#include <cuda_bf16.h>

// ConvQuadInterp3d: register-resident separable 27-max + rare inline solve.
// D split across 2 CTAs (5 output planes each) to halve regs and double grid.
// x: (B=2, CH=1, D=10, H=512, W=512) fp32
// out: coords (B,1,3,D,H,W) then y_max (B,1,D,H,W), concatenated fp32.

#define Bb 2
#define Dd 10
#define Hh 512
#define Ww 512
#define PLANE (Hh * Ww)     // 262144
#define WCOLS 18            // ceil(512 / 30)
#define STRIP 8
#define NW 8                // warps per block
#define DSPAN 5             // output planes per CTA
#define DP (DSPAN + 2)      // loaded planes incl. halo = 7

__device__ __forceinline__ int clampi(int v, int lo, int hi) {
    return min(max(v, lo), hi);
}

__global__ __launch_bounds__(256)
void cqi_kernel(const float* __restrict__ x, float* __restrict__ out)
{
    const int lane  = threadIdx.x;                 // 0..31
    const int wid   = threadIdx.y;                 // 0..7
    const int c     = blockIdx.x;                  // 0..17 warp-columns
    const int strip = blockIdx.y * NW + wid;       // 0..63
    const int b     = blockIdx.z >> 1;
    const int d0    = (blockIdx.z & 1) * DSPAN;    // 0 or 5
    const int h0    = strip * STRIP;
    const int w     = c * 30 + lane - 1;           // lanes 0,31 are halo
    const int wc    = clampi(w, 0, Ww - 1);
    const bool valid = (lane >= 1) && (lane <= 30) && (w < Ww);

    const float* xb = x + b * Dd * PLANE;
    float* ymax = out + Bb * 3 * Dd * PLANE;

    // Clamped plane offsets for the 7-plane window [d0-1, d0+5]
    int zoff[DP];
    #pragma unroll
    for (int j = 0; j < DP; ++j)
        zoff[j] = clampi(d0 - 1 + j, 0, Dd - 1) * PLANE;

    float x0[DP], zm1[DSPAN], z0[DSPAN];

    // Prologue: rows h0-1 (zmax only) and h0 (raw + zmax)
    {
        const float* p = xb + clampi(h0 - 1, 0, Hh - 1) * Ww + wc;
        float t[DP];
        #pragma unroll
        for (int j = 0; j < DP; ++j) t[j] = __ldg(p + zoff[j]);
        #pragma unroll
        for (int k = 0; k < DSPAN; ++k)
            zm1[k] = fmaxf(fmaxf(t[k], t[k + 1]), t[k + 2]);
        p = xb + h0 * Ww + wc;
        #pragma unroll
        for (int j = 0; j < DP; ++j) x0[j] = __ldg(p + zoff[j]);
        #pragma unroll
        for (int k = 0; k < DSPAN; ++k)
            z0[k] = fmaxf(fmaxf(x0[k], x0[k + 1]), x0[k + 2]);
    }

    #pragma unroll 1
    for (int hh = 0; hh < STRIP; ++hh) {
        const int h = h0 + hh;

        // Load row h+1 (clamped), fold z
        const float* p = xb + clampi(h + 1, 0, Hh - 1) * Ww + wc;
        float xn[DP], zp1[DSPAN];
        #pragma unroll
        for (int j = 0; j < DP; ++j) xn[j] = __ldg(p + zoff[j]);
        #pragma unroll
        for (int k = 0; k < DSPAN; ++k)
            zp1[k] = fmaxf(fmaxf(xn[k], xn[k + 1]), xn[k + 2]);

        const int hb = h * Ww + w;
        float* c0p = out + (b * 3 + 0) * Dd * PLANE + hb;
        float* c1p = out + (b * 3 + 1) * Dd * PLANE + hb;
        float* c2p = out + (b * 3 + 2) * Dd * PLANE + hb;
        float* yp  = ymax + b * Dd * PLANE + hb;

        unsigned mask = 0u;

        #pragma unroll
        for (int k = 0; k < DSPAN; ++k) {
            const int d = d0 + k;
            // full 3x3 (z,y) column max at own w (shared with neighbors via shfl)
            const float cmf = fmaxf(fmaxf(zm1[k], z0[k]), zp1[k]);
            const float Lv = __shfl_up_sync(0xFFFFFFFFu, cmf, 1);
            const float Rv = __shfl_down_sync(0xFFFFFFFFu, cmf, 1);
            // own-column neighbors excluding center (z halo comes from raw planes)
            const float zpn = fmaxf(x0[k], x0[k + 2]);
            float nm = fmaxf(fmaxf(zm1[k], zp1[k]), zpn);
            nm = fmaxf(nm, fmaxf(Lv, Rv));
            nm = fmaxf(nm, 0.0f);
            const float cc = x0[k + 1];
            if (valid) {
                if (cc > nm) mask |= 1u << k;
                c0p[d * PLANE] = (float)d;
                c1p[d * PLANE] = (float)h;
                c2p[d * PLANE] = (float)w;
                yp [d * PLANE] = cc;
            }
        }

        // Rare path: quadratic refinement at strict maxima (single code copy)
        while (mask) {
            const int k = __ffs(mask) - 1;
            mask &= mask - 1u;
            const int d = d0 + k;

            int zo[3], yo[3], xo[3];
            #pragma unroll
            for (int j = 0; j < 3; ++j) {
                zo[j] = clampi(d - 1 + j, 0, Dd - 1) * PLANE;
                yo[j] = clampi(h - 1 + j, 0, Hh - 1) * Ww;
                xo[j] = clampi(w - 1 + j, 0, Ww - 1);
            }
            #define V(z, y, xx) __ldg(xb + zo[z] + yo[y] + xo[xx])
            const float cc   = V(1,1,1);
            const float v110 = V(1,1,0), v112 = V(1,1,2);
            const float v101 = V(1,0,1), v121 = V(1,2,1);
            const float v011 = V(0,1,1), v211 = V(2,1,1);
            const float v100 = V(1,0,0), v122 = V(1,2,2), v120 = V(1,2,0), v102 = V(1,0,2);
            const float v001 = V(0,0,1), v221 = V(2,2,1), v201 = V(2,0,1), v021 = V(0,2,1);
            const float v010 = V(0,1,0), v212 = V(2,1,2), v210 = V(2,1,0), v012 = V(0,1,2);
            #undef V

            const float gx = 0.5f * (v112 - v110);
            const float gy = 0.5f * (v121 - v101);
            const float gs = 0.5f * (v211 - v011);
            const float h00 = v110 + v112 - 2.0f * cc;
            const float h11 = v101 + v121 - 2.0f * cc;
            const float h22 = v011 + v211 - 2.0f * cc;
            const float h01 = 0.25f * (v100 + v122 - v120 - v102);
            const float h12 = 0.25f * (v001 + v221 - v201 - v021);
            const float h02 = 0.25f * (v010 + v212 - v210 - v012);
            const float h10 = h01, h20 = h02, h21 = h12;
            const float b0 = gx, b1 = gy, b2 = gs;

            const float c00 = h11 * h22 - h12 * h21;
            const float c01 = h10 * h22 - h12 * h20;
            const float c02 = h10 * h21 - h11 * h20;
            const float det = h00 * c00 - h01 * c01 + h02 * c02;
            const float inv = 1.0f / det;

            const float t0 = b1 * h22 - h12 * b2;
            const float t1 = b1 * h21 - h11 * b2;
            const float t2 = h10 * b2 - b1 * h20;

            const float sx = (b0 * c00 - h01 * t0 + h02 * t1) * inv;
            const float sy = (h00 * t0 - b0 * c01 + h02 * t2) * inv;
            const float ss = (h00 * (h11 * b2 - h21 * b1)
                            - h01 * (h10 * b2 - h20 * b1)
                            + b0 * c02) * inv;

            float dx0 = -sx, dx1 = -sy, dx2 = -ss;
            const float mag = fmaxf(fmaxf(fabsf(dx0), fabsf(dx1)), fabsf(dx2));
            if (mag > 0.7f) { dx0 = 0.0f; dx1 = 0.0f; dx2 = 0.0f; }

            const float dy_ = 0.5f * (gx * dx0 + gy * dx1 + gs * dx2);
            const float yv  = cc + dy_ + 10.0f;

            c0p[d * PLANE] = (float)d + dx2;
            c1p[d * PLANE] = (float)h + dx1;
            c2p[d * PLANE] = (float)w + dx0;
            yp [d * PLANE] = yv;
        }

        // Rotate rolling state
        #pragma unroll
        for (int k = 0; k < DSPAN; ++k) {
            zm1[k] = z0[k];
            z0[k]  = zp1[k];
        }
        #pragma unroll
        for (int j = 0; j < DP; ++j) x0[j] = xn[j];
    }
}

extern "C" void kernel_launch(void* const* d_in, const int* in_sizes, int n_in,
                              void* d_out, int out_size)
{
    const float* x = (const float*)d_in[0];
    float* out = (float*)d_out;
    dim3 grid(WCOLS, Hh / STRIP / NW, Bb * 2);   // (18, 8, 4)
    dim3 block(32, NW);                          // 256 threads
    cqi_kernel<<<grid, block>>>(x, out);
}

// round 9
// speedup vs baseline: 1.5329x; 1.0741x over previous
#include <cuda_runtime.h>
#include <cuda_bf16.h>

// ConvQuadInterp3d: register-resident separable 27-max; maxima queued per-warp
// and solved 32-at-a-time (warp-cooperative) after each strip.
// x: (B=2, CH=1, D=10, H=512, W=512) fp32
// out: coords (B,1,3,D,H,W) then y_max (B,1,D,H,W), concatenated fp32.

#define Bb 2
#define Dd 10
#define Hh 512
#define Ww 512
#define PLANE (Hh * Ww)     // 262144
#define WCOLS 18            // ceil(512 / 30)
#define STRIP 8
#define NW 8                // warps per block
#define DSPAN 5             // output planes per CTA
#define DP (DSPAN + 2)      // loaded planes incl. halo = 7
#define QCAP 392            // >= 8*45 + 31 (independent-set bound on maxima)

__device__ __forceinline__ int clampi(int v, int lo, int hi) {
    return min(max(v, lo), hi);
}

__global__ __launch_bounds__(256)
void cqi_kernel(const float* __restrict__ x, float* __restrict__ out)
{
    __shared__ unsigned q[NW][QCAP];

    const int lane  = threadIdx.x;                 // 0..31
    const int wid   = threadIdx.y;                 // 0..7
    const int c     = blockIdx.x;                  // 0..17 warp-columns
    const int strip = blockIdx.y * NW + wid;       // 0..63
    const int b     = blockIdx.z >> 1;
    const int d0    = (blockIdx.z & 1) * DSPAN;    // 0 or 5
    const int h0    = strip * STRIP;
    const int w     = c * 30 + lane - 1;           // lanes 0,31 are halo
    const int wc    = clampi(w, 0, Ww - 1);
    const bool valid = (lane >= 1) && (lane <= 30) && (w < Ww);

    const float* xb = x + b * Dd * PLANE;
    float* ymax = out + Bb * 3 * Dd * PLANE;

    // Clamped plane offsets for the 7-plane window [d0-1, d0+5]
    int zoff[DP];
    #pragma unroll
    for (int j = 0; j < DP; ++j)
        zoff[j] = clampi(d0 - 1 + j, 0, Dd - 1) * PLANE;

    float x0[DP], zm1[DSPAN], z0[DSPAN];

    // Prologue: rows h0-1 (zmax only) and h0 (raw + zmax)
    {
        const float* p = xb + clampi(h0 - 1, 0, Hh - 1) * Ww + wc;
        float t[DP];
        #pragma unroll
        for (int j = 0; j < DP; ++j) t[j] = __ldg(p + zoff[j]);
        #pragma unroll
        for (int k = 0; k < DSPAN; ++k)
            zm1[k] = fmaxf(fmaxf(t[k], t[k + 1]), t[k + 2]);
        p = xb + h0 * Ww + wc;
        #pragma unroll
        for (int j = 0; j < DP; ++j) x0[j] = __ldg(p + zoff[j]);
        #pragma unroll
        for (int k = 0; k < DSPAN; ++k)
            z0[k] = fmaxf(fmaxf(x0[k], x0[k + 1]), x0[k + 2]);
    }

    unsigned cnt = 0;  // warp-uniform queue count

    #pragma unroll 1
    for (int hh = 0; hh < STRIP; ++hh) {
        const int h = h0 + hh;

        // Load row h+1 (clamped), fold z
        const float* p = xb + clampi(h + 1, 0, Hh - 1) * Ww + wc;
        float xn[DP], zp1[DSPAN];
        #pragma unroll
        for (int j = 0; j < DP; ++j) xn[j] = __ldg(p + zoff[j]);
        #pragma unroll
        for (int k = 0; k < DSPAN; ++k)
            zp1[k] = fmaxf(fmaxf(xn[k], xn[k + 1]), xn[k + 2]);

        const int hb = h * Ww + w;
        float* c0p = out + (b * 3 + 0) * Dd * PLANE + hb;
        float* c1p = out + (b * 3 + 1) * Dd * PLANE + hb;
        float* c2p = out + (b * 3 + 2) * Dd * PLANE + hb;
        float* yp  = ymax + b * Dd * PLANE + hb;

        unsigned mask = 0u;

        #pragma unroll
        for (int k = 0; k < DSPAN; ++k) {
            const int d = d0 + k;
            // full 3x3 (z,y) column max at own w (shared with neighbors via shfl)
            const float cmf = fmaxf(fmaxf(zm1[k], z0[k]), zp1[k]);
            const float Lv = __shfl_up_sync(0xFFFFFFFFu, cmf, 1);
            const float Rv = __shfl_down_sync(0xFFFFFFFFu, cmf, 1);
            // own-column neighbors excluding center (z halo from raw planes)
            const float zpn = fmaxf(x0[k], x0[k + 2]);
            float nm = fmaxf(fmaxf(zm1[k], zp1[k]), zpn);
            nm = fmaxf(nm, fmaxf(Lv, Rv));
            nm = fmaxf(nm, 0.0f);
            const float cc = x0[k + 1];
            if (valid) {
                if (cc > nm) mask |= 1u << k;
                c0p[d * PLANE] = (float)d;
                c1p[d * PLANE] = (float)h;
                c2p[d * PLANE] = (float)w;
                yp [d * PLANE] = cc;
            }
        }

        // Push maxima into warp-private queue (ballot + prefix, no atomics)
        #pragma unroll
        for (int k = 0; k < DSPAN; ++k) {
            const unsigned bit = (mask >> k) & 1u;
            const unsigned bal = __ballot_sync(0xFFFFFFFFu, bit);
            if (bal) {
                const unsigned pos = cnt + __popc(bal & ((1u << lane) - 1u));
                if (bit) q[wid][pos] = (unsigned)((hh << 8) | (k << 5) | lane);
                cnt += __popc(bal);
            }
        }

        // Rotate rolling state
        #pragma unroll
        for (int k = 0; k < DSPAN; ++k) {
            zm1[k] = z0[k];
            z0[k]  = zp1[k];
        }
        #pragma unroll
        for (int j = 0; j < DP; ++j) x0[j] = xn[j];
    }

    // Warp-cooperative solve: 32 maxima at a time, one per lane
    for (unsigned base = 0; base < cnt; base += 32u) {
        const unsigned idx = base + lane;
        if (idx < cnt) {
            const unsigned e = q[wid][idx];
            const int hh = (int)(e >> 8);
            const int k  = (int)((e >> 5) & 7u);
            const int ln = (int)(e & 31u);
            const int d  = d0 + k;
            const int h  = h0 + hh;
            const int we = c * 30 + ln - 1;

            int zo[3], yo[3], xo[3];
            #pragma unroll
            for (int j = 0; j < 3; ++j) {
                zo[j] = clampi(d - 1 + j, 0, Dd - 1) * PLANE;
                yo[j] = clampi(h - 1 + j, 0, Hh - 1) * Ww;
                xo[j] = clampi(we - 1 + j, 0, Ww - 1);
            }
            #define V(z, y, xx) __ldg(xb + zo[z] + yo[y] + xo[xx])
            const float cc   = V(1,1,1);
            const float v110 = V(1,1,0), v112 = V(1,1,2);
            const float v101 = V(1,0,1), v121 = V(1,2,1);
            const float v011 = V(0,1,1), v211 = V(2,1,1);
            const float v100 = V(1,0,0), v122 = V(1,2,2), v120 = V(1,2,0), v102 = V(1,0,2);
            const float v001 = V(0,0,1), v221 = V(2,2,1), v201 = V(2,0,1), v021 = V(0,2,1);
            const float v010 = V(0,1,0), v212 = V(2,1,2), v210 = V(2,1,0), v012 = V(0,1,2);
            #undef V

            const float gx = 0.5f * (v112 - v110);
            const float gy = 0.5f * (v121 - v101);
            const float gs = 0.5f * (v211 - v011);
            const float h00 = v110 + v112 - 2.0f * cc;
            const float h11 = v101 + v121 - 2.0f * cc;
            const float h22 = v011 + v211 - 2.0f * cc;
            const float h01 = 0.25f * (v100 + v122 - v120 - v102);
            const float h12 = 0.25f * (v001 + v221 - v201 - v021);
            const float h02 = 0.25f * (v010 + v212 - v210 - v012);
            const float h10 = h01, h20 = h02, h21 = h12;
            const float b0 = gx, b1 = gy, b2 = gs;

            const float c00 = h11 * h22 - h12 * h21;
            const float c01 = h10 * h22 - h12 * h20;
            const float c02 = h10 * h21 - h11 * h20;
            const float det = h00 * c00 - h01 * c01 + h02 * c02;
            const float inv = 1.0f / det;

            const float t0 = b1 * h22 - h12 * b2;
            const float t1 = b1 * h21 - h11 * b2;
            const float t2 = h10 * b2 - b1 * h20;

            const float sx = (b0 * c00 - h01 * t0 + h02 * t1) * inv;
            const float sy = (h00 * t0 - b0 * c01 + h02 * t2) * inv;
            const float ss = (h00 * (h11 * b2 - h21 * b1)
                            - h01 * (h10 * b2 - h20 * b1)
                            + b0 * c02) * inv;

            float dx0 = -sx, dx1 = -sy, dx2 = -ss;
            const float mag = fmaxf(fmaxf(fabsf(dx0), fabsf(dx1)), fabsf(dx2));
            if (mag > 0.7f) { dx0 = 0.0f; dx1 = 0.0f; dx2 = 0.0f; }

            const float dy_ = 0.5f * (gx * dx0 + gy * dx1 + gs * dx2);
            const float yv  = cc + dy_ + 10.0f;

            const int basep = d * PLANE + h * Ww + we;
            out[(b * 3 + 0) * Dd * PLANE + basep] = (float)d + dx2;
            out[(b * 3 + 1) * Dd * PLANE + basep] = (float)h + dx1;
            out[(b * 3 + 2) * Dd * PLANE + basep] = (float)we + dx0;
            ymax[b * Dd * PLANE + basep] = yv;
        }
    }
}

extern "C" void kernel_launch(void* const* d_in, const int* in_sizes, int n_in,
                              void* d_out, int out_size)
{
    const float* x = (const float*)d_in[0];
    float* out = (float*)d_out;
    dim3 grid(WCOLS, Hh / STRIP / NW, Bb * 2);   // (18, 8, 4)
    dim3 block(32, NW);                          // 256 threads
    cqi_kernel<<<grid, block>>>(x, out);
}